// round 7
// baseline (speedup 1.0000x reference)
#include <cuda_runtime.h>
#include <stdint.h>

// ---------------------------------------------------------------------------
// FakeQuant (global min/max), split kernels.
//
// Key change this round: output stores use st.global.wt (__stwt) so the
// 205MB write stream does NOT allocate in L2. Without write churn, the
// x-region left resident by the reduce pass survives the whole apply pass:
//   reduce (forward):  low region __ldcs (streaming), top ~104MB default
//   apply  (backward): __ldcs reads (top region hits L2), __stwt writes
//
//   out = rint((x - mn)*scale)/scale + mn,  scale = 255/(mx - mn)
//   (clip(x, min(x), max(x)) == x, dropped.)
// ---------------------------------------------------------------------------

#define RED_BLOCKS (148 * 8)   // 1184 — best measured apply geometry
#define TPB 256

__device__ float2 g_partials[RED_BLOCKS];  // .x = min, .y = max

__device__ __forceinline__ void acc4(float4 v, float& mn, float& mx) {
    mn = fminf(mn, fminf(fminf(v.x, v.y), fminf(v.z, v.w)));
    mx = fmaxf(mx, fmaxf(fmaxf(v.x, v.y), fmaxf(v.z, v.w)));
}

__device__ __forceinline__ float4 fq4(float4 v, float mn, float scale, float inv) {
    float4 r;
    r.x = fmaf(rintf((v.x - mn) * scale), inv, mn);
    r.y = fmaf(rintf((v.y - mn) * scale), inv, mn);
    r.z = fmaf(rintf((v.z - mn) * scale), inv, mn);
    r.w = fmaf(rintf((v.w - mn) * scale), inv, mn);
    return r;
}

// ---------------- reduce: forward sweep --------------------------------------
// [0, keep_thresh):  __ldcs (streaming, evict-first)
// [keep_thresh, n4): default (stays L2-resident for the apply pass)
__global__ void __launch_bounds__(TPB) minmax_reduce_kernel(
    const float4* __restrict__ x4, int n4, int keep_thresh) {
    float mn = 3.402823466e+38f;
    float mx = -3.402823466e+38f;

    const int S = gridDim.x * blockDim.x;
    int i = blockIdx.x * blockDim.x + threadIdx.x;

    for (; i + 3 * S < keep_thresh; i += 4 * S) {
        float4 a = __ldcs(&x4[i]);
        float4 b = __ldcs(&x4[i + S]);
        float4 c = __ldcs(&x4[i + 2 * S]);
        float4 d = __ldcs(&x4[i + 3 * S]);
        acc4(a, mn, mx); acc4(b, mn, mx); acc4(c, mn, mx); acc4(d, mn, mx);
    }
    for (; i < keep_thresh; i += S) acc4(__ldcs(&x4[i]), mn, mx);

    for (; i + 3 * S < n4; i += 4 * S) {
        float4 a = x4[i];
        float4 b = x4[i + S];
        float4 c = x4[i + 2 * S];
        float4 d = x4[i + 3 * S];
        acc4(a, mn, mx); acc4(b, mn, mx); acc4(c, mn, mx); acc4(d, mn, mx);
    }
    for (; i < n4; i += S) acc4(x4[i], mn, mx);

    // warp + block reduce
    #pragma unroll
    for (int off = 16; off > 0; off >>= 1) {
        mn = fminf(mn, __shfl_xor_sync(0xFFFFFFFFu, mn, off));
        mx = fmaxf(mx, __shfl_xor_sync(0xFFFFFFFFu, mx, off));
    }
    __shared__ float s_mn[TPB / 32];
    __shared__ float s_mx[TPB / 32];
    int wid = threadIdx.x >> 5;
    int lid = threadIdx.x & 31;
    if (lid == 0) { s_mn[wid] = mn; s_mx[wid] = mx; }
    __syncthreads();
    if (wid == 0) {
        const int nw = TPB / 32;
        mn = (lid < nw) ? s_mn[lid] : 3.402823466e+38f;
        mx = (lid < nw) ? s_mx[lid] : -3.402823466e+38f;
        #pragma unroll
        for (int off = 4; off > 0; off >>= 1) {
            mn = fminf(mn, __shfl_xor_sync(0xFFFFFFFFu, mn, off));
            mx = fmaxf(mx, __shfl_xor_sync(0xFFFFFFFFu, mx, off));
        }
        if (lid == 0) g_partials[blockIdx.x] = make_float2(mn, mx);
    }
}

// Parallel prologue: reduce g_partials within a block, broadcast via smem.
__device__ __forceinline__ void reduce_partials_block(float& out_mn, float& out_mx) {
    float mn = 3.402823466e+38f;
    float mx = -3.402823466e+38f;
    for (int p = threadIdx.x; p < RED_BLOCKS; p += blockDim.x) {
        float2 v = g_partials[p];
        mn = fminf(mn, v.x);
        mx = fmaxf(mx, v.y);
    }
    #pragma unroll
    for (int off = 16; off > 0; off >>= 1) {
        mn = fminf(mn, __shfl_xor_sync(0xFFFFFFFFu, mn, off));
        mx = fmaxf(mx, __shfl_xor_sync(0xFFFFFFFFu, mx, off));
    }
    __shared__ float s_mn[TPB / 32];
    __shared__ float s_mx[TPB / 32];
    int wid = threadIdx.x >> 5;
    int lid = threadIdx.x & 31;
    if (lid == 0) { s_mn[wid] = mn; s_mx[wid] = mx; }
    __syncthreads();
    __shared__ float s_fmn, s_fmx;
    if (wid == 0) {
        const int nw = TPB / 32;
        mn = (lid < nw) ? s_mn[lid] : 3.402823466e+38f;
        mx = (lid < nw) ? s_mx[lid] : -3.402823466e+38f;
        #pragma unroll
        for (int off = 4; off > 0; off >>= 1) {
            mn = fminf(mn, __shfl_xor_sync(0xFFFFFFFFu, mn, off));
            mx = fmaxf(mx, __shfl_xor_sync(0xFFFFFFFFu, mx, off));
        }
        if (lid == 0) { s_fmn = mn; s_fmx = mx; }
    }
    __syncthreads();
    out_mn = s_fmn;
    out_mx = s_fmx;
}

// ---------------- apply: backward sweep, __ldcs reads, __stwt writes --------
__global__ void __launch_bounds__(TPB) fakequant_apply_kernel(
    const float4* __restrict__ x4, float4* __restrict__ out4, int n4) {
    float mn, mx;
    reduce_partials_block(mn, mx);
    const float scale = 255.0f / (mx - mn);
    const float inv   = 1.0f / scale;

    const int S = gridDim.x * blockDim.x;
    const int gtid = blockIdx.x * blockDim.x + threadIdx.x;
    if (gtid >= n4) return;

    int k = (n4 - 1 - gtid) / S;  // highest valid stride index for this thread

    for (; k >= 3; k -= 4) {
        int i0 = gtid + k * S;
        int i1 = i0 - S;
        int i2 = i0 - 2 * S;
        int i3 = i0 - 3 * S;
        float4 a = __ldcs(&x4[i0]);
        float4 b = __ldcs(&x4[i1]);
        float4 c = __ldcs(&x4[i2]);
        float4 d = __ldcs(&x4[i3]);
        __stwt(&out4[i0], fq4(a, mn, scale, inv));
        __stwt(&out4[i1], fq4(b, mn, scale, inv));
        __stwt(&out4[i2], fq4(c, mn, scale, inv));
        __stwt(&out4[i3], fq4(d, mn, scale, inv));
    }
    for (; k >= 0; --k) {
        int i0 = gtid + k * S;
        __stwt(&out4[i0], fq4(__ldcs(&x4[i0]), mn, scale, inv));
    }
}

// Scalar tail (never hit for this shape: n % 1024 == 0; kept for generality).
__global__ void fakequant_tail_kernel(const float* __restrict__ x,
                                      float* __restrict__ out,
                                      int start, int n) {
    float mn = 3.402823466e+38f;
    float mx = -3.402823466e+38f;
    for (int p = 0; p < RED_BLOCKS; ++p) {
        float2 v = g_partials[p];
        mn = fminf(mn, v.x);
        mx = fmaxf(mx, v.y);
    }
    const float scale = 255.0f / (mx - mn);
    const float inv   = 1.0f / scale;
    int i = start + blockIdx.x * blockDim.x + threadIdx.x;
    if (i < n) out[i] = fmaf(rintf((x[i] - mn) * scale), inv, mn);
}

extern "C" void kernel_launch(void* const* d_in, const int* in_sizes, int n_in,
                              void* d_out, int out_size) {
    const float* x = (const float*)d_in[0];
    float* out = (float*)d_out;
    int n = in_sizes[0];
    int n4 = n >> 2;
    int tail_start = n4 << 2;

    // Keep the TOP ~104MB of x default-policy in reduce (L2 is ~126MB and,
    // with __stwt writes, apply no longer churns it).
    const long long KEEP_BYTES = 104LL * 1024 * 1024;
    int keep_elems = (int)(KEEP_BYTES / 16);            // float4s
    int keep_thresh = n4 > keep_elems ? n4 - keep_elems : 0;

    minmax_reduce_kernel<<<RED_BLOCKS, TPB>>>((const float4*)x, n4, keep_thresh);
    fakequant_apply_kernel<<<RED_BLOCKS, TPB>>>((const float4*)x, (float4*)out, n4);

    if (tail_start < n) {
        int tail = n - tail_start;
        fakequant_tail_kernel<<<(tail + TPB - 1) / TPB, TPB>>>(x, out, tail_start, n);
    }
}

// round 8
// speedup vs baseline: 1.0875x; 1.0875x over previous
#include <cuda_runtime.h>
#include <stdint.h>

// ---------------------------------------------------------------------------
// FakeQuant (global min/max) — round-3 structure (best measured) with
// 8-wide load/store batching for longer same-direction DRAM bursts.
//
//   reduce (forward):  low region __ldcs (streaming), top ~112MB default
//                      (stays L2-resident for the apply pass)
//   apply  (backward): __ldcs reads (top region hits L2 first), __stcs writes
//
//   out = rint((x - mn)*scale)/scale + mn,  scale = 255/(mx - mn)
//   (clip(x, min(x), max(x)) == x, dropped.)
// ---------------------------------------------------------------------------

#define RED_BLOCKS (148 * 8)   // 1184
#define TPB 256

__device__ float2 g_partials[RED_BLOCKS];  // .x = min, .y = max

__device__ __forceinline__ void acc4(float4 v, float& mn, float& mx) {
    mn = fminf(mn, fminf(fminf(v.x, v.y), fminf(v.z, v.w)));
    mx = fmaxf(mx, fmaxf(fmaxf(v.x, v.y), fmaxf(v.z, v.w)));
}

__device__ __forceinline__ float4 fq4(float4 v, float mn, float scale, float inv) {
    float4 r;
    r.x = fmaf(rintf((v.x - mn) * scale), inv, mn);
    r.y = fmaf(rintf((v.y - mn) * scale), inv, mn);
    r.z = fmaf(rintf((v.z - mn) * scale), inv, mn);
    r.w = fmaf(rintf((v.w - mn) * scale), inv, mn);
    return r;
}

// ---------------- reduce: forward sweep --------------------------------------
__global__ void __launch_bounds__(TPB) minmax_reduce_kernel(
    const float4* __restrict__ x4, int n4, int keep_thresh) {
    float mn = 3.402823466e+38f;
    float mx = -3.402823466e+38f;

    const int S = gridDim.x * blockDim.x;
    int i = blockIdx.x * blockDim.x + threadIdx.x;

    // Low region: streaming loads, 8 outstanding.
    for (; i + 7 * S < keep_thresh; i += 8 * S) {
        float4 v0 = __ldcs(&x4[i]);
        float4 v1 = __ldcs(&x4[i + S]);
        float4 v2 = __ldcs(&x4[i + 2 * S]);
        float4 v3 = __ldcs(&x4[i + 3 * S]);
        float4 v4 = __ldcs(&x4[i + 4 * S]);
        float4 v5 = __ldcs(&x4[i + 5 * S]);
        float4 v6 = __ldcs(&x4[i + 6 * S]);
        float4 v7 = __ldcs(&x4[i + 7 * S]);
        acc4(v0, mn, mx); acc4(v1, mn, mx); acc4(v2, mn, mx); acc4(v3, mn, mx);
        acc4(v4, mn, mx); acc4(v5, mn, mx); acc4(v6, mn, mx); acc4(v7, mn, mx);
    }
    for (; i < keep_thresh; i += S) acc4(__ldcs(&x4[i]), mn, mx);

    // Top region: default policy — stays in L2 for apply.
    for (; i + 7 * S < n4; i += 8 * S) {
        float4 v0 = x4[i];
        float4 v1 = x4[i + S];
        float4 v2 = x4[i + 2 * S];
        float4 v3 = x4[i + 3 * S];
        float4 v4 = x4[i + 4 * S];
        float4 v5 = x4[i + 5 * S];
        float4 v6 = x4[i + 6 * S];
        float4 v7 = x4[i + 7 * S];
        acc4(v0, mn, mx); acc4(v1, mn, mx); acc4(v2, mn, mx); acc4(v3, mn, mx);
        acc4(v4, mn, mx); acc4(v5, mn, mx); acc4(v6, mn, mx); acc4(v7, mn, mx);
    }
    for (; i < n4; i += S) acc4(x4[i], mn, mx);

    // warp + block reduce
    #pragma unroll
    for (int off = 16; off > 0; off >>= 1) {
        mn = fminf(mn, __shfl_xor_sync(0xFFFFFFFFu, mn, off));
        mx = fmaxf(mx, __shfl_xor_sync(0xFFFFFFFFu, mx, off));
    }
    __shared__ float s_mn[TPB / 32];
    __shared__ float s_mx[TPB / 32];
    int wid = threadIdx.x >> 5;
    int lid = threadIdx.x & 31;
    if (lid == 0) { s_mn[wid] = mn; s_mx[wid] = mx; }
    __syncthreads();
    if (wid == 0) {
        const int nw = TPB / 32;
        mn = (lid < nw) ? s_mn[lid] : 3.402823466e+38f;
        mx = (lid < nw) ? s_mx[lid] : -3.402823466e+38f;
        #pragma unroll
        for (int off = 4; off > 0; off >>= 1) {
            mn = fminf(mn, __shfl_xor_sync(0xFFFFFFFFu, mn, off));
            mx = fmaxf(mx, __shfl_xor_sync(0xFFFFFFFFu, mx, off));
        }
        if (lid == 0) g_partials[blockIdx.x] = make_float2(mn, mx);
    }
}

// Parallel prologue: reduce g_partials within a block, broadcast via smem.
__device__ __forceinline__ void reduce_partials_block(float& out_mn, float& out_mx) {
    float mn = 3.402823466e+38f;
    float mx = -3.402823466e+38f;
    for (int p = threadIdx.x; p < RED_BLOCKS; p += blockDim.x) {
        float2 v = g_partials[p];
        mn = fminf(mn, v.x);
        mx = fmaxf(mx, v.y);
    }
    #pragma unroll
    for (int off = 16; off > 0; off >>= 1) {
        mn = fminf(mn, __shfl_xor_sync(0xFFFFFFFFu, mn, off));
        mx = fmaxf(mx, __shfl_xor_sync(0xFFFFFFFFu, mx, off));
    }
    __shared__ float s_mn[TPB / 32];
    __shared__ float s_mx[TPB / 32];
    int wid = threadIdx.x >> 5;
    int lid = threadIdx.x & 31;
    if (lid == 0) { s_mn[wid] = mn; s_mx[wid] = mx; }
    __syncthreads();
    __shared__ float s_fmn, s_fmx;
    if (wid == 0) {
        const int nw = TPB / 32;
        mn = (lid < nw) ? s_mn[lid] : 3.402823466e+38f;
        mx = (lid < nw) ? s_mx[lid] : -3.402823466e+38f;
        #pragma unroll
        for (int off = 4; off > 0; off >>= 1) {
            mn = fminf(mn, __shfl_xor_sync(0xFFFFFFFFu, mn, off));
            mx = fmaxf(mx, __shfl_xor_sync(0xFFFFFFFFu, mx, off));
        }
        if (lid == 0) { s_fmn = mn; s_fmx = mx; }
    }
    __syncthreads();
    out_mn = s_fmn;
    out_mx = s_fmx;
}

// ---------------- apply: backward sweep, 8 loads then 8 stores --------------
__global__ void __launch_bounds__(TPB) fakequant_apply_kernel(
    const float4* __restrict__ x4, float4* __restrict__ out4, int n4) {
    float mn, mx;
    reduce_partials_block(mn, mx);
    const float scale = 255.0f / (mx - mn);
    const float inv   = 1.0f / scale;

    const int S = gridDim.x * blockDim.x;
    const int gtid = blockIdx.x * blockDim.x + threadIdx.x;
    if (gtid >= n4) return;

    int k = (n4 - 1 - gtid) / S;  // highest valid stride index for this thread

    for (; k >= 7; k -= 8) {
        int i0 = gtid + k * S;
        float4 v0 = __ldcs(&x4[i0]);
        float4 v1 = __ldcs(&x4[i0 - S]);
        float4 v2 = __ldcs(&x4[i0 - 2 * S]);
        float4 v3 = __ldcs(&x4[i0 - 3 * S]);
        float4 v4 = __ldcs(&x4[i0 - 4 * S]);
        float4 v5 = __ldcs(&x4[i0 - 5 * S]);
        float4 v6 = __ldcs(&x4[i0 - 6 * S]);
        float4 v7 = __ldcs(&x4[i0 - 7 * S]);
        __stcs(&out4[i0],         fq4(v0, mn, scale, inv));
        __stcs(&out4[i0 - S],     fq4(v1, mn, scale, inv));
        __stcs(&out4[i0 - 2 * S], fq4(v2, mn, scale, inv));
        __stcs(&out4[i0 - 3 * S], fq4(v3, mn, scale, inv));
        __stcs(&out4[i0 - 4 * S], fq4(v4, mn, scale, inv));
        __stcs(&out4[i0 - 5 * S], fq4(v5, mn, scale, inv));
        __stcs(&out4[i0 - 6 * S], fq4(v6, mn, scale, inv));
        __stcs(&out4[i0 - 7 * S], fq4(v7, mn, scale, inv));
    }
    for (; k >= 0; --k) {
        int i0 = gtid + k * S;
        __stcs(&out4[i0], fq4(__ldcs(&x4[i0]), mn, scale, inv));
    }
}

// Scalar tail (never hit for this shape: n % 1024 == 0; kept for generality).
__global__ void fakequant_tail_kernel(const float* __restrict__ x,
                                      float* __restrict__ out,
                                      int start, int n) {
    float mn = 3.402823466e+38f;
    float mx = -3.402823466e+38f;
    for (int p = 0; p < RED_BLOCKS; ++p) {
        float2 v = g_partials[p];
        mn = fminf(mn, v.x);
        mx = fmaxf(mx, v.y);
    }
    const float scale = 255.0f / (mx - mn);
    const float inv   = 1.0f / scale;
    int i = start + blockIdx.x * blockDim.x + threadIdx.x;
    if (i < n) out[i] = fmaf(rintf((x[i] - mn) * scale), inv, mn);
}

extern "C" void kernel_launch(void* const* d_in, const int* in_sizes, int n_in,
                              void* d_out, int out_size) {
    const float* x = (const float*)d_in[0];
    float* out = (float*)d_out;
    int n = in_sizes[0];
    int n4 = n >> 2;
    int tail_start = n4 << 2;

    // Keep the TOP ~112MB of x default-policy in reduce (L2 is ~126MB).
    const long long KEEP_BYTES = 112LL * 1024 * 1024;
    int keep_elems = (int)(KEEP_BYTES / 16);  // float4s
    int keep_thresh = n4 > keep_elems ? n4 - keep_elems : 0;

    minmax_reduce_kernel<<<RED_BLOCKS, TPB>>>((const float4*)x, n4, keep_thresh);
    fakequant_apply_kernel<<<RED_BLOCKS, TPB>>>((const float4*)x, (float4*)out, n4);

    if (tail_start < n) {
        int tail = n - tail_start;
        fakequant_tail_kernel<<<(tail + TPB - 1) / TPB, TPB>>>(x, out, tail_start, n);
    }
}

// round 9
// speedup vs baseline: 1.0879x; 1.0003x over previous
#include <cuda_runtime.h>
#include <stdint.h>

// ---------------------------------------------------------------------------
// FakeQuant (global min/max), split kernels — consolidated best config:
//
//   reduce (forward):  low region __ldcs (streaming), top ~112MB default
//                      (stays L2-resident for the apply pass). The LAST
//                      finishing block folds all per-block partials into a
//                      single float2 g_final (atomic-counter detection,
//                      self-resetting for CUDA-graph replay).
//   apply  (backward): reads g_final (2 words, L2-broadcast), then streams:
//                      __ldcs reads (top region hits L2 first), __stcs writes.
//                      4-wide unroll (measured best: 61.1us vs 62.6 for 8-wide).
//
//   out = rint((x - mn)*scale)/scale + mn,  scale = 255/(mx - mn)
//   (clip(x, min(x), max(x)) == x, dropped.)
// ---------------------------------------------------------------------------

#define RED_BLOCKS (148 * 8)   // 1184
#define TPB 256

__device__ float2       g_partials[RED_BLOCKS];  // .x = min, .y = max
__device__ float2       g_final;                 // folded (min, max)
__device__ unsigned int g_done_count = 0;        // self-resetting

__device__ __forceinline__ void acc4(float4 v, float& mn, float& mx) {
    mn = fminf(mn, fminf(fminf(v.x, v.y), fminf(v.z, v.w)));
    mx = fmaxf(mx, fmaxf(fmaxf(v.x, v.y), fmaxf(v.z, v.w)));
}

__device__ __forceinline__ float4 fq4(float4 v, float mn, float scale, float inv) {
    float4 r;
    r.x = fmaf(rintf((v.x - mn) * scale), inv, mn);
    r.y = fmaf(rintf((v.y - mn) * scale), inv, mn);
    r.z = fmaf(rintf((v.z - mn) * scale), inv, mn);
    r.w = fmaf(rintf((v.w - mn) * scale), inv, mn);
    return r;
}

// ---------------- reduce: forward sweep --------------------------------------
__global__ void __launch_bounds__(TPB) minmax_reduce_kernel(
    const float4* __restrict__ x4, int n4, int keep_thresh) {
    float mn = 3.402823466e+38f;
    float mx = -3.402823466e+38f;

    const int S = gridDim.x * blockDim.x;
    int i = blockIdx.x * blockDim.x + threadIdx.x;

    // Low region: streaming loads.
    for (; i + 3 * S < keep_thresh; i += 4 * S) {
        float4 a = __ldcs(&x4[i]);
        float4 b = __ldcs(&x4[i + S]);
        float4 c = __ldcs(&x4[i + 2 * S]);
        float4 d = __ldcs(&x4[i + 3 * S]);
        acc4(a, mn, mx); acc4(b, mn, mx); acc4(c, mn, mx); acc4(d, mn, mx);
    }
    for (; i < keep_thresh; i += S) acc4(__ldcs(&x4[i]), mn, mx);

    // Top region: default policy — stays in L2 for apply.
    for (; i + 3 * S < n4; i += 4 * S) {
        float4 a = x4[i];
        float4 b = x4[i + S];
        float4 c = x4[i + 2 * S];
        float4 d = x4[i + 3 * S];
        acc4(a, mn, mx); acc4(b, mn, mx); acc4(c, mn, mx); acc4(d, mn, mx);
    }
    for (; i < n4; i += S) acc4(x4[i], mn, mx);

    // warp + block reduce
    #pragma unroll
    for (int off = 16; off > 0; off >>= 1) {
        mn = fminf(mn, __shfl_xor_sync(0xFFFFFFFFu, mn, off));
        mx = fmaxf(mx, __shfl_xor_sync(0xFFFFFFFFu, mx, off));
    }
    __shared__ float s_mn[TPB / 32];
    __shared__ float s_mx[TPB / 32];
    int wid = threadIdx.x >> 5;
    int lid = threadIdx.x & 31;
    if (lid == 0) { s_mn[wid] = mn; s_mx[wid] = mx; }
    __syncthreads();
    if (wid == 0) {
        const int nw = TPB / 32;
        mn = (lid < nw) ? s_mn[lid] : 3.402823466e+38f;
        mx = (lid < nw) ? s_mx[lid] : -3.402823466e+38f;
        #pragma unroll
        for (int off = 4; off > 0; off >>= 1) {
            mn = fminf(mn, __shfl_xor_sync(0xFFFFFFFFu, mn, off));
            mx = fmaxf(mx, __shfl_xor_sync(0xFFFFFFFFu, mx, off));
        }
        if (lid == 0) g_partials[blockIdx.x] = make_float2(mn, mx);
    }

    // Last-finishing block folds all partials into g_final.
    __shared__ bool s_last;
    __syncthreads();
    if (threadIdx.x == 0) {
        __threadfence();  // publish this block's partial
        unsigned int prev = atomicAdd(&g_done_count, 1u);
        s_last = (prev == (unsigned int)(gridDim.x - 1));
        if (s_last) g_done_count = 0;  // reset for next graph replay
    }
    __syncthreads();
    if (s_last) {
        float fmn = 3.402823466e+38f;
        float fmx = -3.402823466e+38f;
        for (int p = threadIdx.x; p < RED_BLOCKS; p += TPB) {
            float2 v = g_partials[p];
            fmn = fminf(fmn, v.x);
            fmx = fmaxf(fmx, v.y);
        }
        #pragma unroll
        for (int off = 16; off > 0; off >>= 1) {
            fmn = fminf(fmn, __shfl_xor_sync(0xFFFFFFFFu, fmn, off));
            fmx = fmaxf(fmx, __shfl_xor_sync(0xFFFFFFFFu, fmx, off));
        }
        if (lid == 0) { s_mn[wid] = fmn; s_mx[wid] = fmx; }
        __syncthreads();
        if (threadIdx.x == 0) {
            #pragma unroll
            for (int w = 1; w < TPB / 32; ++w) {
                fmn = fminf(s_mn[0], fminf(fmn, s_mn[w]));
                fmx = fmaxf(s_mx[0], fmaxf(fmx, s_mx[w]));
            }
            g_final = make_float2(fmn, fmx);
        }
    }
}

// ---------------- apply: backward sweep, 4-wide (measured best) -------------
__global__ void __launch_bounds__(TPB) fakequant_apply_kernel(
    const float4* __restrict__ x4, float4* __restrict__ out4, int n4) {
    const float2 f = g_final;          // 2-word L2-broadcast read
    const float mn    = f.x;
    const float scale = 255.0f / (f.y - f.x);
    const float inv   = 1.0f / scale;

    const int S = gridDim.x * blockDim.x;
    const int gtid = blockIdx.x * blockDim.x + threadIdx.x;
    if (gtid >= n4) return;

    int k = (n4 - 1 - gtid) / S;  // highest valid stride index for this thread

    for (; k >= 3; k -= 4) {
        int i0 = gtid + k * S;
        int i1 = i0 - S;
        int i2 = i0 - 2 * S;
        int i3 = i0 - 3 * S;
        float4 a = __ldcs(&x4[i0]);
        float4 b = __ldcs(&x4[i1]);
        float4 c = __ldcs(&x4[i2]);
        float4 d = __ldcs(&x4[i3]);
        __stcs(&out4[i0], fq4(a, mn, scale, inv));
        __stcs(&out4[i1], fq4(b, mn, scale, inv));
        __stcs(&out4[i2], fq4(c, mn, scale, inv));
        __stcs(&out4[i3], fq4(d, mn, scale, inv));
    }
    for (; k >= 0; --k) {
        int i0 = gtid + k * S;
        __stcs(&out4[i0], fq4(__ldcs(&x4[i0]), mn, scale, inv));
    }
}

// Scalar tail (never hit for this shape: n % 1024 == 0; kept for generality).
__global__ void fakequant_tail_kernel(const float* __restrict__ x,
                                      float* __restrict__ out,
                                      int start, int n) {
    float2 f = g_final;
    const float mn    = f.x;
    const float scale = 255.0f / (f.y - f.x);
    const float inv   = 1.0f / scale;
    int i = start + blockIdx.x * blockDim.x + threadIdx.x;
    if (i < n) out[i] = fmaf(rintf((x[i] - mn) * scale), inv, mn);
}

extern "C" void kernel_launch(void* const* d_in, const int* in_sizes, int n_in,
                              void* d_out, int out_size) {
    const float* x = (const float*)d_in[0];
    float* out = (float*)d_out;
    int n = in_sizes[0];
    int n4 = n >> 2;
    int tail_start = n4 << 2;

    // Keep the TOP ~112MB of x default-policy in reduce (L2 is ~126MB).
    const long long KEEP_BYTES = 112LL * 1024 * 1024;
    int keep_elems = (int)(KEEP_BYTES / 16);  // float4s
    int keep_thresh = n4 > keep_elems ? n4 - keep_elems : 0;

    minmax_reduce_kernel<<<RED_BLOCKS, TPB>>>((const float4*)x, n4, keep_thresh);
    fakequant_apply_kernel<<<RED_BLOCKS, TPB>>>((const float4*)x, (float4*)out, n4);

    if (tail_start < n) {
        int tail = n - tail_start;
        fakequant_tail_kernel<<<(tail + TPB - 1) / TPB, TPB>>>(x, out, tail_start, n);
    }
}